// round 14
// baseline (speedup 1.0000x reference)
#include <cuda_runtime.h>
#include <math.h>

#define NB   16
#define NC   2
#define NS   2
#define NF   257
#define NHALF 256
#define HOP  128
#define PADN 256
#define NFRM 2501
#define NT   320000

#define YT_N ((size_t)NB * NS * NC * NT)          // 20,480,000 floats (y_time)
#define YB_E ((size_t)NB * NS * NF * NFRM)        // 20,568,224 complex elements
#define YB_N (YB_E * 2)                           // 41,136,448 floats (re+im)

#define SWZ(k) ((k) ^ (((k) >> 2) & 12))
#define PIO256 0.012271846303085129f   // pi/256
#define CW (-0.012271846303085129f)    // -2*pi/512

// epilogue geometry: combine = 10000 work-blocks, transpose = 9*79*64 = 45504
#define NCOMB 10000
#define TGX 9
#define TGY 79
#define NTRANS (TGX * TGY * NB * NS)   // 45504
#define EGROUPS 5056                    // 45504 / 9
#define EBLOCKS (EGROUPS * 11)          // 55616

// ---------------- device scratch ----------------
__device__ float2 g_Y[(size_t)NB * NS * NFRM * NF];          // beamformed STFT [b][s][t][f]
__device__ float2 g_frames2[(size_t)NB * NS * NFRM * NHALF]; // windowed irfft frames (pairs)

__device__ __forceinline__ float2 cadd(float2 a, float2 b) { return make_float2(a.x + b.x, a.y + b.y); }
__device__ __forceinline__ float2 csub(float2 a, float2 b) { return make_float2(a.x - b.x, a.y - b.y); }
__device__ __forceinline__ float2 cmul(float2 a, float2 w) {
    return make_float2(a.x * w.x - a.y * w.y, a.x * w.y + a.y * w.x);
}

__device__ __forceinline__ int reflect_idx(int i) {
    i = (i < 0) ? -i : i;
    return (i >= NT) ? (2 * NT - 2 - i) : i;
}

// ============ FUSED: STFT + beamform + inverse rfft + window; one block/(b,t) ============
// (byte-identical to R13 champion)
__global__ __launch_bounds__(128) void k_fused(
    const float* __restrict__ x,
    const float* __restrict__ sr, const float* __restrict__ si
) {
    int bt = blockIdx.x;
    int b = bt / NFRM, t = bt - b * NFRM;
    int tid = threadIdx.x;
    int c = tid >> 6, j = tid & 63;

    __shared__ float2 buf[2][2][NHALF];
    __shared__ float2 sX[2][NF];
    __shared__ float2 sY[2][NF];

    float wl[4], wh[4], ucs[4], usn[4];
#pragma unroll
    for (int q = 0; q < 4; q++) {
        int k = j + 64 * q;
        wl[q] = 0.5f - 0.5f * __cosf(PIO256 * (float)(2 * k));
        wh[q] = 0.5f - 0.5f * __cosf(PIO256 * (float)(2 * k + 1));
        __sincosf(CW * (float)k, &usn[q], &ucs[q]);
    }
    float fcs[3], fsn[3];
    {
        int tb1 = (j & 3) << 5, tb2 = (j & 15) << 3, tb3 = j << 1;
        __sincosf(CW * (float)tb1, &fsn[0], &fcs[0]);
        __sincosf(CW * (float)tb2, &fsn[1], &fcs[1]);
        __sincosf(CW * (float)tb3, &fsn[2], &fcs[2]);
    }

    const float* xin = x + (size_t)(b * NC + c) * NT;
    int base = t * HOP - PADN;
    float2 v[4];
    if (t >= 2 && t <= 2498) {
        const float2* x2 = (const float2*)(xin + base);
#pragma unroll
        for (int q = 0; q < 4; q++) {
            float2 xx = x2[j + 64 * q];
            v[q] = make_float2(xx.x * wl[q], xx.y * wh[q]);
        }
    } else {
#pragma unroll
        for (int q = 0; q < 4; q++) {
            int i0 = base + 2 * (j + 64 * q);
            v[q] = make_float2(xin[reflect_idx(i0)] * wl[q],
                               xin[reflect_idx(i0 + 1)] * wh[q]);
        }
    }

    {
        float2 s0 = cadd(v[0], v[2]), d0 = csub(v[0], v[2]);
        float2 s1 = cadd(v[1], v[3]), d1 = csub(v[1], v[3]);
        float2 c0 = cadd(s0, s1);
        float2 c1 = make_float2(d0.x + d1.y, d0.y - d1.x);
        float2 c2 = csub(s0, s1);
        float2 c3 = make_float2(d0.x - d1.y, d0.y + d1.x);
        float4* dst = (float4*)&buf[c][0][SWZ(4 * j)];
        dst[0] = make_float4(c0.x, c0.y, c1.x, c1.y);
        dst[1] = make_float4(c2.x, c2.y, c3.x, c3.y);
    }
    __syncthreads();

    int p = 0;
#pragma unroll
    for (int st = 1; st < 4; st++) {
        int Ns = 1 << (2 * st);
        int r = j & (Ns - 1);
        float2 w1 = make_float2(fcs[st - 1], fsn[st - 1]);
        float2 w2 = cmul(w1, w1);
        float2 w3 = cmul(w2, w1);
        float2 a0 = buf[c][p][SWZ(j)];
        float2 a1 = cmul(buf[c][p][SWZ(j + 64)],  w1);
        float2 a2 = cmul(buf[c][p][SWZ(j + 128)], w2);
        float2 a3 = cmul(buf[c][p][SWZ(j + 192)], w3);
        float2 s0 = cadd(a0, a2), d0 = csub(a0, a2);
        float2 s1 = cadd(a1, a3), d1 = csub(a1, a3);
        int bse = ((j >> (2 * st)) << (2 * st + 2)) + r;
        buf[c][p ^ 1][SWZ(bse)]          = cadd(s0, s1);
        buf[c][p ^ 1][SWZ(bse + Ns)]     = make_float2(d0.x + d1.y, d0.y - d1.x);
        buf[c][p ^ 1][SWZ(bse + 2 * Ns)] = csub(s0, s1);
        buf[c][p ^ 1][SWZ(bse + 3 * Ns)] = make_float2(d0.x - d1.y, d0.y + d1.x);
        p ^= 1;
        __syncthreads();
    }

#pragma unroll
    for (int q = 0; q < 4; q++) {
        int k = j + 64 * q;
        float2 Zk = buf[c][p][SWZ(k)];
        float2 Zm = buf[c][p][SWZ((256 - k) & 255)];
        float Ex = 0.5f * (Zk.x + Zm.x), Ey = 0.5f * (Zk.y - Zm.y);
        float Dx = 0.5f * (Zk.x - Zm.x), Dy = 0.5f * (Zk.y + Zm.y);
        float Ox = Dy, Oy = -Dx;
        sX[c][k] = make_float2(Ex + (Ox * ucs[q] - Oy * usn[q]),
                               Ey + (Ox * usn[q] + Oy * ucs[q]));
    }
    if (j == 0) {
        float2 Z0 = buf[c][p][SWZ(0)];
        sX[c][256] = make_float2(Z0.x - Z0.y, 0.0f);
    }
    __syncthreads();

    float2* Yout = g_Y + ((size_t)(b * NS) * NFRM + t) * NF;
    for (int item = tid; item < NS * NF; item += 128) {
        int s = (item >= NF);
        int k = item - s * NF;
        float2 arv = ((const float2*)sr)[item];
        float2 aiv = ((const float2*)si)[item];
        float inv = 1.0f / (arv.x * arv.x + aiv.x * aiv.x +
                            arv.y * arv.y + aiv.y * aiv.y);
        float2 X0 = sX[0][k], X1 = sX[1][k];
        float2 y = make_float2(
            inv * (arv.x * X0.x + aiv.x * X0.y + arv.y * X1.x + aiv.y * X1.y),
            inv * (arv.x * X0.y - aiv.x * X0.x + arv.y * X1.y - aiv.y * X1.x));
        sY[s][k] = y;
        Yout[(size_t)s * NFRM * NF + k] = y;
    }
    __syncthreads();

    int s = c;
    float2 z[4];
#pragma unroll
    for (int q = 0; q < 4; q++) {
        int k = j + 64 * q;
        float2 Xk = sY[s][k];
        float2 Xm = sY[s][256 - k];
        if (k == 0) { Xk.y = 0.0f; Xm.y = 0.0f; }
        float Ex = 0.5f * (Xk.x + Xm.x), Ey = 0.5f * (Xk.y - Xm.y);
        float Dx = 0.5f * (Xk.x - Xm.x), Dy = 0.5f * (Xk.y + Xm.y);
        float Ox = Dx * ucs[q] + Dy * usn[q];
        float Oy = Dy * ucs[q] - Dx * usn[q];
        z[q] = make_float2(Ex - Oy, Ey + Ox);
    }
    {
        float2 s0 = cadd(z[0], z[2]), d0 = csub(z[0], z[2]);
        float2 s1 = cadd(z[1], z[3]), d1 = csub(z[1], z[3]);
        float2 c0 = cadd(s0, s1);
        float2 c1 = make_float2(d0.x - d1.y, d0.y + d1.x);
        float2 c2 = csub(s0, s1);
        float2 c3 = make_float2(d0.x + d1.y, d0.y - d1.x);
        float4* dst = (float4*)&buf[s][0][SWZ(4 * j)];
        dst[0] = make_float4(c0.x, c0.y, c1.x, c1.y);
        dst[1] = make_float4(c2.x, c2.y, c3.x, c3.y);
    }
    __syncthreads();

    p = 0;
#pragma unroll
    for (int st = 1; st < 3; st++) {
        int Ns = 1 << (2 * st);
        int r = j & (Ns - 1);
        float2 w1 = make_float2(fcs[st - 1], -fsn[st - 1]);
        float2 w2 = cmul(w1, w1);
        float2 w3 = cmul(w2, w1);
        float2 a0 = buf[s][p][SWZ(j)];
        float2 a1 = cmul(buf[s][p][SWZ(j + 64)],  w1);
        float2 a2 = cmul(buf[s][p][SWZ(j + 128)], w2);
        float2 a3 = cmul(buf[s][p][SWZ(j + 192)], w3);
        float2 s0 = cadd(a0, a2), d0 = csub(a0, a2);
        float2 s1 = cadd(a1, a3), d1 = csub(a1, a3);
        int bse = ((j >> (2 * st)) << (2 * st + 2)) + r;
        buf[s][p ^ 1][SWZ(bse)]          = cadd(s0, s1);
        buf[s][p ^ 1][SWZ(bse + Ns)]     = make_float2(d0.x - d1.y, d0.y + d1.x);
        buf[s][p ^ 1][SWZ(bse + 2 * Ns)] = csub(s0, s1);
        buf[s][p ^ 1][SWZ(bse + 3 * Ns)] = make_float2(d0.x + d1.y, d0.y - d1.x);
        p ^= 1;
        __syncthreads();
    }

    {
        float2 w1 = make_float2(fcs[2], -fsn[2]);
        float2 w2 = cmul(w1, w1);
        float2 w3 = cmul(w2, w1);
        float2 a0 = buf[s][p][SWZ(j)];
        float2 a1 = cmul(buf[s][p][SWZ(j + 64)],  w1);
        float2 a2 = cmul(buf[s][p][SWZ(j + 128)], w2);
        float2 a3 = cmul(buf[s][p][SWZ(j + 192)], w3);
        float2 s0 = cadd(a0, a2), d0 = csub(a0, a2);
        float2 s1 = cadd(a1, a3), d1 = csub(a1, a3);
        float2 cc[4];
        cc[0] = cadd(s0, s1);
        cc[1] = make_float2(d0.x - d1.y, d0.y + d1.x);
        cc[2] = csub(s0, s1);
        cc[3] = make_float2(d0.x + d1.y, d0.y - d1.x);
        float2* fout = g_frames2 + ((size_t)(b * NS + s) * NFRM + t) * NHALF;
        const float sc = 1.0f / 256.0f;
#pragma unroll
        for (int q = 0; q < 4; q++) {
            fout[j + 64 * q] = make_float2(cc[q].x * sc * wl[q],
                                           cc[q].y * sc * wh[q]);
        }
    }
}

// ============ EPILOGUE: transpose + overlap-add merged, interleaved 2:9 ============
__global__ __launch_bounds__(256) void k_epilogue(
    float* __restrict__ yt, unsigned long long ytCap, int doYt,
    float* __restrict__ reOut, float* __restrict__ imOut,
    unsigned long long planeCap, int doYb
) {
    __shared__ float2 tile[32][33];
    int bid = blockIdx.x;
    int grp = bid / 11, u = bid - grp * 11;

    if (u < 2) {
        // ---------- combine (overlap-add), work-block ci ----------
        int ci = grp * 2 + u;
        if (ci >= NCOMB || !doYt) return;
        int idx = ci * 256 + threadIdx.x;
        const int quarter = NT / 4;
        int bs = idx / quarter;
        int mo = (idx - bs * quarter) * 4;
        int m = mo + PADN;
        int klo = m - 384;
        klo = (klo < 0) ? 0 : (klo >> 7);
        int khi = m >> 7;
        if (khi > NFRM - 1) khi = NFRM - 1;
        const float4* fr4 = (const float4*)(g_frames2 + (size_t)bs * NFRM * NHALF);
        float y0 = 0, y1 = 0, y2 = 0, y3 = 0;
        for (int k = klo; k <= khi; k++) {
            int r = m - (k << 7);
            float4 vv = fr4[k * 128 + (r >> 2)];
            y0 += vv.x; y1 += vv.y; y2 += vv.z; y3 += vv.w;
        }
        float4 out;
        if (mo >= 128 && mo <= 319868) {
            const float inv = 2.0f / 3.0f;  // Hann^2 COLA envelope = 3/2
            out = make_float4(y0 * inv, y1 * inv, y2 * inv, y3 * inv);
        } else {
            float e0 = 0, e1 = 0, e2 = 0, e3 = 0;
            for (int k = klo; k <= khi; k++) {
                int r = m - (k << 7);
                float a0 = 0.5f - 0.5f * __cosf(PIO256 * (float)r);
                float a1 = 0.5f - 0.5f * __cosf(PIO256 * (float)(r + 1));
                float a2 = 0.5f - 0.5f * __cosf(PIO256 * (float)(r + 2));
                float a3 = 0.5f - 0.5f * __cosf(PIO256 * (float)(r + 3));
                e0 += a0 * a0; e1 += a1 * a1; e2 += a2 * a2; e3 += a3 * a3;
            }
            out = make_float4(y0 / e0, y1 / e1, y2 / e2, y3 / e3);
        }
        size_t i0 = (size_t)(bs * 2) * NT + mo;
        size_t i1 = (size_t)(bs * 2 + 1) * NT + mo;
        if (i0 + 3 < ytCap) *(float4*)(yt + i0) = out;
        if (i1 + 3 < ytCap) *(float4*)(yt + i1) = out;
    } else {
        // ---------- transpose, work-block ti ----------
        int ti = grp * 9 + (u - 2);
        if (ti >= NTRANS || !doYb) return;
        int bs = ti / (TGX * TGY);
        int r2 = ti - bs * (TGX * TGY);
        int tyb = r2 / TGX;
        int fxb = r2 - tyb * TGX;
        int f0 = fxb << 5, t0 = tyb << 5;
        int tx = threadIdx.x & 31, ty = threadIdx.x >> 5;
        const float2* src = g_Y + (size_t)bs * NFRM * NF;
#pragma unroll
        for (int i = 0; i < 4; i++) {
            int tt = t0 + ty + i * 8, ff = f0 + tx;
            if (tt < NFRM && ff < NF)
                tile[ty + i * 8][tx] = src[(size_t)tt * NF + ff];
        }
        __syncthreads();
        size_t dbase = (size_t)bs * NF * NFRM;
#pragma unroll
        for (int i = 0; i < 4; i++) {
            int ff = f0 + ty + i * 8, tt = t0 + tx;
            if (ff < NF && tt < NFRM) {
                size_t di = dbase + (size_t)ff * NFRM + tt;
                if (di < planeCap) {
                    float2 vv = tile[tx][ty + i * 8];
                    reOut[di] = vv.x;
                    if (imOut) imOut[di] = vv.y;
                }
            }
        }
    }
}

// ---------------- launcher ----------------
extern "C" void kernel_launch(void* const* d_in, const int* in_sizes, int n_in,
                              void* d_out, int out_size) {
    const float* x = 0; const float* small[2] = {0, 0}; int nsmall = 0;
    for (int i = 0; i < n_in && i < 3; i++) {
        if (in_sizes[i] > 1000000) x = (const float*)d_in[i];
        else if (nsmall < 2) small[nsmall++] = (const float*)d_in[i];
    }
    const float* sr = small[0] ? small[0] : (const float*)d_in[1];
    const float* si = small[1] ? small[1] : (const float*)d_in[2];
    if (!x) x = (const float*)d_in[0];

    size_t osz = (size_t)out_size;
    float* base = (float*)d_out;

    float* yt = 0;  unsigned long long ytCap = 0;
    float* re = 0;  float* im = 0;  unsigned long long planeCap = 0;

    if (osz == YT_N + YB_N) {
        yt = base;              ytCap = YT_N;
        re = base + YT_N;       im = base + YT_N + YB_E;   planeCap = YB_E;
    } else if (osz == YT_N + YB_E) {
        yt = base;              ytCap = YT_N;
        re = base + YT_N;       im = 0;                    planeCap = YB_E;
    } else if (osz == YT_N) {
        yt = base;              ytCap = YT_N;
    } else if (osz == YB_N) {
        re = base;              im = base + YB_E;          planeCap = YB_E;
    } else if (osz == YB_E) {
        re = base;              im = 0;                    planeCap = YB_E;
    } else {
        yt = base;              ytCap = (osz < YT_N) ? osz : YT_N;
        if (osz > YT_N) {
            size_t rem = osz - YT_N;
            re = base + YT_N;
            if (rem >= 2 * YB_E) { im = base + YT_N + YB_E; planeCap = YB_E; }
            else                 { im = 0; planeCap = rem; }
        }
    }

    k_fused<<<NB * NFRM, 128>>>(x, sr, si);
    k_epilogue<<<EBLOCKS, 256>>>(yt, ytCap, yt != 0, re, im, planeCap, re != 0);
}

// round 15
// speedup vs baseline: 1.0012x; 1.0012x over previous
#include <cuda_runtime.h>
#include <math.h>

#define NB   16
#define NC   2
#define NS   2
#define NF   257
#define NHALF 256
#define HOP  128
#define PADN 256
#define NFRM 2501
#define NT   320000

#define YT_N ((size_t)NB * NS * NC * NT)          // 20,480,000 floats (y_time)
#define YB_E ((size_t)NB * NS * NF * NFRM)        // 20,568,224 complex elements
#define YB_N (YB_E * 2)                           // 41,136,448 floats (re+im)

#define SWZ(k) ((k) ^ (((k) >> 2) & 12))
#define PIO256 0.012271846303085129f   // pi/256
#define CW (-0.012271846303085129f)    // -2*pi/512

// ---------------- device scratch ----------------
__device__ float2 g_Y[(size_t)NB * NS * NFRM * NF];          // beamformed STFT [b][s][t][f]
__device__ float2 g_frames2[(size_t)NB * NS * NFRM * NHALF]; // windowed irfft frames (pairs)

__device__ __forceinline__ float2 cadd(float2 a, float2 b) { return make_float2(a.x + b.x, a.y + b.y); }
__device__ __forceinline__ float2 csub(float2 a, float2 b) { return make_float2(a.x - b.x, a.y - b.y); }
__device__ __forceinline__ float2 cmul(float2 a, float2 w) {
    return make_float2(a.x * w.x - a.y * w.y, a.x * w.y + a.y * w.x);
}

__device__ __forceinline__ int reflect_idx(int i) {
    i = (i < 0) ? -i : i;
    return (i >= NT) ? (2 * NT - 2 - i) : i;
}

// ============ FUSED: STFT + beamform + inverse rfft + window; one block/(b,t) ============
// R13 champion + minBlocksPerMultiprocessor=10 (regs 56 -> <=51, 9 -> 10 blocks/SM)
__global__ __launch_bounds__(128, 10) void k_fused(
    const float* __restrict__ x,
    const float* __restrict__ sr, const float* __restrict__ si
) {
    int bt = blockIdx.x;
    int b = bt / NFRM, t = bt - b * NFRM;
    int tid = threadIdx.x;
    int c = tid >> 6, j = tid & 63;

    __shared__ float2 buf[2][2][NHALF];
    __shared__ float2 sX[2][NF];
    __shared__ float2 sY[2][NF];

    float wl[4], wh[4], ucs[4], usn[4];
#pragma unroll
    for (int q = 0; q < 4; q++) {
        int k = j + 64 * q;
        wl[q] = 0.5f - 0.5f * __cosf(PIO256 * (float)(2 * k));
        wh[q] = 0.5f - 0.5f * __cosf(PIO256 * (float)(2 * k + 1));
        __sincosf(CW * (float)k, &usn[q], &ucs[q]);
    }
    float fcs[3], fsn[3];
    {
        int tb1 = (j & 3) << 5, tb2 = (j & 15) << 3, tb3 = j << 1;
        __sincosf(CW * (float)tb1, &fsn[0], &fcs[0]);
        __sincosf(CW * (float)tb2, &fsn[1], &fcs[1]);
        __sincosf(CW * (float)tb3, &fsn[2], &fcs[2]);
    }

    const float* xin = x + (size_t)(b * NC + c) * NT;
    int base = t * HOP - PADN;
    float2 v[4];
    if (t >= 2 && t <= 2498) {
        const float2* x2 = (const float2*)(xin + base);
#pragma unroll
        for (int q = 0; q < 4; q++) {
            float2 xx = x2[j + 64 * q];
            v[q] = make_float2(xx.x * wl[q], xx.y * wh[q]);
        }
    } else {
#pragma unroll
        for (int q = 0; q < 4; q++) {
            int i0 = base + 2 * (j + 64 * q);
            v[q] = make_float2(xin[reflect_idx(i0)] * wl[q],
                               xin[reflect_idx(i0 + 1)] * wh[q]);
        }
    }

    {
        float2 s0 = cadd(v[0], v[2]), d0 = csub(v[0], v[2]);
        float2 s1 = cadd(v[1], v[3]), d1 = csub(v[1], v[3]);
        float2 c0 = cadd(s0, s1);
        float2 c1 = make_float2(d0.x + d1.y, d0.y - d1.x);
        float2 c2 = csub(s0, s1);
        float2 c3 = make_float2(d0.x - d1.y, d0.y + d1.x);
        float4* dst = (float4*)&buf[c][0][SWZ(4 * j)];
        dst[0] = make_float4(c0.x, c0.y, c1.x, c1.y);
        dst[1] = make_float4(c2.x, c2.y, c3.x, c3.y);
    }
    __syncthreads();

    int p = 0;
#pragma unroll
    for (int st = 1; st < 4; st++) {
        int Ns = 1 << (2 * st);
        int r = j & (Ns - 1);
        float2 w1 = make_float2(fcs[st - 1], fsn[st - 1]);
        float2 w2 = cmul(w1, w1);
        float2 w3 = cmul(w2, w1);
        float2 a0 = buf[c][p][SWZ(j)];
        float2 a1 = cmul(buf[c][p][SWZ(j + 64)],  w1);
        float2 a2 = cmul(buf[c][p][SWZ(j + 128)], w2);
        float2 a3 = cmul(buf[c][p][SWZ(j + 192)], w3);
        float2 s0 = cadd(a0, a2), d0 = csub(a0, a2);
        float2 s1 = cadd(a1, a3), d1 = csub(a1, a3);
        int bse = ((j >> (2 * st)) << (2 * st + 2)) + r;
        buf[c][p ^ 1][SWZ(bse)]          = cadd(s0, s1);
        buf[c][p ^ 1][SWZ(bse + Ns)]     = make_float2(d0.x + d1.y, d0.y - d1.x);
        buf[c][p ^ 1][SWZ(bse + 2 * Ns)] = csub(s0, s1);
        buf[c][p ^ 1][SWZ(bse + 3 * Ns)] = make_float2(d0.x - d1.y, d0.y + d1.x);
        p ^= 1;
        __syncthreads();
    }

#pragma unroll
    for (int q = 0; q < 4; q++) {
        int k = j + 64 * q;
        float2 Zk = buf[c][p][SWZ(k)];
        float2 Zm = buf[c][p][SWZ((256 - k) & 255)];
        float Ex = 0.5f * (Zk.x + Zm.x), Ey = 0.5f * (Zk.y - Zm.y);
        float Dx = 0.5f * (Zk.x - Zm.x), Dy = 0.5f * (Zk.y + Zm.y);
        float Ox = Dy, Oy = -Dx;
        sX[c][k] = make_float2(Ex + (Ox * ucs[q] - Oy * usn[q]),
                               Ey + (Ox * usn[q] + Oy * ucs[q]));
    }
    if (j == 0) {
        float2 Z0 = buf[c][p][SWZ(0)];
        sX[c][256] = make_float2(Z0.x - Z0.y, 0.0f);
    }
    __syncthreads();

    float2* Yout = g_Y + ((size_t)(b * NS) * NFRM + t) * NF;
    for (int item = tid; item < NS * NF; item += 128) {
        int s = (item >= NF);
        int k = item - s * NF;
        float2 arv = ((const float2*)sr)[item];
        float2 aiv = ((const float2*)si)[item];
        float inv = 1.0f / (arv.x * arv.x + aiv.x * aiv.x +
                            arv.y * arv.y + aiv.y * aiv.y);
        float2 X0 = sX[0][k], X1 = sX[1][k];
        float2 y = make_float2(
            inv * (arv.x * X0.x + aiv.x * X0.y + arv.y * X1.x + aiv.y * X1.y),
            inv * (arv.x * X0.y - aiv.x * X0.x + arv.y * X1.y - aiv.y * X1.x));
        sY[s][k] = y;
        Yout[(size_t)s * NFRM * NF + k] = y;
    }
    __syncthreads();

    int s = c;
    float2 z[4];
#pragma unroll
    for (int q = 0; q < 4; q++) {
        int k = j + 64 * q;
        float2 Xk = sY[s][k];
        float2 Xm = sY[s][256 - k];
        if (k == 0) { Xk.y = 0.0f; Xm.y = 0.0f; }
        float Ex = 0.5f * (Xk.x + Xm.x), Ey = 0.5f * (Xk.y - Xm.y);
        float Dx = 0.5f * (Xk.x - Xm.x), Dy = 0.5f * (Xk.y + Xm.y);
        float Ox = Dx * ucs[q] + Dy * usn[q];
        float Oy = Dy * ucs[q] - Dx * usn[q];
        z[q] = make_float2(Ex - Oy, Ey + Ox);
    }
    {
        float2 s0 = cadd(z[0], z[2]), d0 = csub(z[0], z[2]);
        float2 s1 = cadd(z[1], z[3]), d1 = csub(z[1], z[3]);
        float2 c0 = cadd(s0, s1);
        float2 c1 = make_float2(d0.x - d1.y, d0.y + d1.x);
        float2 c2 = csub(s0, s1);
        float2 c3 = make_float2(d0.x + d1.y, d0.y - d1.x);
        float4* dst = (float4*)&buf[s][0][SWZ(4 * j)];
        dst[0] = make_float4(c0.x, c0.y, c1.x, c1.y);
        dst[1] = make_float4(c2.x, c2.y, c3.x, c3.y);
    }
    __syncthreads();

    p = 0;
#pragma unroll
    for (int st = 1; st < 3; st++) {
        int Ns = 1 << (2 * st);
        int r = j & (Ns - 1);
        float2 w1 = make_float2(fcs[st - 1], -fsn[st - 1]);
        float2 w2 = cmul(w1, w1);
        float2 w3 = cmul(w2, w1);
        float2 a0 = buf[s][p][SWZ(j)];
        float2 a1 = cmul(buf[s][p][SWZ(j + 64)],  w1);
        float2 a2 = cmul(buf[s][p][SWZ(j + 128)], w2);
        float2 a3 = cmul(buf[s][p][SWZ(j + 192)], w3);
        float2 s0 = cadd(a0, a2), d0 = csub(a0, a2);
        float2 s1 = cadd(a1, a3), d1 = csub(a1, a3);
        int bse = ((j >> (2 * st)) << (2 * st + 2)) + r;
        buf[s][p ^ 1][SWZ(bse)]          = cadd(s0, s1);
        buf[s][p ^ 1][SWZ(bse + Ns)]     = make_float2(d0.x - d1.y, d0.y + d1.x);
        buf[s][p ^ 1][SWZ(bse + 2 * Ns)] = csub(s0, s1);
        buf[s][p ^ 1][SWZ(bse + 3 * Ns)] = make_float2(d0.x + d1.y, d0.y - d1.x);
        p ^= 1;
        __syncthreads();
    }

    {
        float2 w1 = make_float2(fcs[2], -fsn[2]);
        float2 w2 = cmul(w1, w1);
        float2 w3 = cmul(w2, w1);
        float2 a0 = buf[s][p][SWZ(j)];
        float2 a1 = cmul(buf[s][p][SWZ(j + 64)],  w1);
        float2 a2 = cmul(buf[s][p][SWZ(j + 128)], w2);
        float2 a3 = cmul(buf[s][p][SWZ(j + 192)], w3);
        float2 s0 = cadd(a0, a2), d0 = csub(a0, a2);
        float2 s1 = cadd(a1, a3), d1 = csub(a1, a3);
        float2 cc[4];
        cc[0] = cadd(s0, s1);
        cc[1] = make_float2(d0.x - d1.y, d0.y + d1.x);
        cc[2] = csub(s0, s1);
        cc[3] = make_float2(d0.x + d1.y, d0.y - d1.x);
        float2* fout = g_frames2 + ((size_t)(b * NS + s) * NFRM + t) * NHALF;
        const float sc = 1.0f / 256.0f;
#pragma unroll
        for (int q = 0; q < 4; q++) {
            fout[j + 64 * q] = make_float2(cc[q].x * sc * wl[q],
                                           cc[q].y * sc * wh[q]);
        }
    }
}

// ---------------- transpose Y [t][f] -> planar output [f][t] per (b,s) ----------------
__global__ void k_transpose(float* __restrict__ reOut, float* __restrict__ imOut,
                            unsigned long long planeCap) {
    __shared__ float2 tile[32][33];
    int bs = blockIdx.z;
    int f0 = blockIdx.x << 5, t0 = blockIdx.y << 5;
    const float2* src = g_Y + (size_t)bs * NFRM * NF;
#pragma unroll
    for (int i = 0; i < 4; i++) {
        int tt = t0 + threadIdx.y + i * 8, ff = f0 + threadIdx.x;
        if (tt < NFRM && ff < NF)
            tile[threadIdx.y + i * 8][threadIdx.x] = src[(size_t)tt * NF + ff];
    }
    __syncthreads();
    size_t dbase = (size_t)bs * NF * NFRM;
#pragma unroll
    for (int i = 0; i < 4; i++) {
        int ff = f0 + threadIdx.y + i * 8, tt = t0 + threadIdx.x;
        if (ff < NF && tt < NFRM) {
            size_t di = dbase + (size_t)ff * NFRM + tt;
            if (di < planeCap) {
                float2 v = tile[threadIdx.x][threadIdx.y + i * 8];
                reOut[di] = v.x;
                if (imOut) imOut[di] = v.y;
            }
        }
    }
}

// ---------------- overlap-add (4 samples/thread, analytic envelope) ----------------
__global__ void k_combine(float* __restrict__ yt, unsigned long long cap) {
    int idx = blockIdx.x * blockDim.x + threadIdx.x;
    const int quarter = NT / 4;
    if (idx >= NB * NS * quarter) return;
    int bs = idx / quarter;
    int mo = (idx - bs * quarter) * 4;
    int m = mo + PADN;
    int klo = m - 384;
    klo = (klo < 0) ? 0 : (klo >> 7);
    int khi = m >> 7;
    if (khi > NFRM - 1) khi = NFRM - 1;
    const float4* fr4 = (const float4*)(g_frames2 + (size_t)bs * NFRM * NHALF);
    float y0 = 0, y1 = 0, y2 = 0, y3 = 0;
    for (int k = klo; k <= khi; k++) {
        int r = m - (k << 7);   // multiple of 4, <= 508
        float4 vv = fr4[k * 128 + (r >> 2)];
        y0 += vv.x; y1 += vv.y; y2 += vv.z; y3 += vv.w;
    }
    float4 out;
    if (mo >= 128 && mo <= 319868) {
        const float inv = 2.0f / 3.0f;  // Hann^2 COLA envelope = 3/2
        out = make_float4(y0 * inv, y1 * inv, y2 * inv, y3 * inv);
    } else {
        float e0 = 0, e1 = 0, e2 = 0, e3 = 0;
        for (int k = klo; k <= khi; k++) {
            int r = m - (k << 7);
            float a0 = 0.5f - 0.5f * __cosf(PIO256 * (float)r);
            float a1 = 0.5f - 0.5f * __cosf(PIO256 * (float)(r + 1));
            float a2 = 0.5f - 0.5f * __cosf(PIO256 * (float)(r + 2));
            float a3 = 0.5f - 0.5f * __cosf(PIO256 * (float)(r + 3));
            e0 += a0 * a0; e1 += a1 * a1; e2 += a2 * a2; e3 += a3 * a3;
        }
        out = make_float4(y0 / e0, y1 / e1, y2 / e2, y3 / e3);
    }
    size_t i0 = (size_t)(bs * 2) * NT + mo;
    size_t i1 = (size_t)(bs * 2 + 1) * NT + mo;
    if (i0 + 3 < cap) *(float4*)(yt + i0) = out;
    if (i1 + 3 < cap) *(float4*)(yt + i1) = out;
}

// ---------------- launcher ----------------
extern "C" void kernel_launch(void* const* d_in, const int* in_sizes, int n_in,
                              void* d_out, int out_size) {
    const float* x = 0; const float* small[2] = {0, 0}; int nsmall = 0;
    for (int i = 0; i < n_in && i < 3; i++) {
        if (in_sizes[i] > 1000000) x = (const float*)d_in[i];
        else if (nsmall < 2) small[nsmall++] = (const float*)d_in[i];
    }
    const float* sr = small[0] ? small[0] : (const float*)d_in[1];
    const float* si = small[1] ? small[1] : (const float*)d_in[2];
    if (!x) x = (const float*)d_in[0];

    size_t osz = (size_t)out_size;
    float* base = (float*)d_out;

    float* yt = 0;  unsigned long long ytCap = 0;
    float* re = 0;  float* im = 0;  unsigned long long planeCap = 0;

    if (osz == YT_N + YB_N) {
        yt = base;              ytCap = YT_N;
        re = base + YT_N;       im = base + YT_N + YB_E;   planeCap = YB_E;
    } else if (osz == YT_N + YB_E) {
        yt = base;              ytCap = YT_N;
        re = base + YT_N;       im = 0;                    planeCap = YB_E;
    } else if (osz == YT_N) {
        yt = base;              ytCap = YT_N;
    } else if (osz == YB_N) {
        re = base;              im = base + YB_E;          planeCap = YB_E;
    } else if (osz == YB_E) {
        re = base;              im = 0;                    planeCap = YB_E;
    } else {
        yt = base;              ytCap = (osz < YT_N) ? osz : YT_N;
        if (osz > YT_N) {
            size_t rem = osz - YT_N;
            re = base + YT_N;
            if (rem >= 2 * YB_E) { im = base + YT_N + YB_E; planeCap = YB_E; }
            else                 { im = 0; planeCap = rem; }
        }
    }

    k_fused<<<NB * NFRM, 128>>>(x, sr, si);
    if (re) {
        dim3 tg((NF + 31) / 32, (NFRM + 31) / 32, NB * NS);
        k_transpose<<<tg, dim3(32, 8)>>>(re, im, planeCap);
    }
    if (yt) {
        k_combine<<<(NB * NS * (NT / 4) + 255) / 256, 256>>>(yt, ytCap);
    }
}

// round 16
// speedup vs baseline: 1.0302x; 1.0290x over previous
#include <cuda_runtime.h>
#include <math.h>

#define NB   16
#define NC   2
#define NS   2
#define NF   257
#define NHALF 256
#define HOP  128
#define PADN 256
#define NFRM 2501
#define NT   320000

#define YT_N ((size_t)NB * NS * NC * NT)          // 20,480,000 floats (y_time)
#define YB_E ((size_t)NB * NS * NF * NFRM)        // 20,568,224 complex elements
#define YB_N (YB_E * 2)                           // 41,136,448 floats (re+im)

#define SWZ(k) ((k) ^ (((k) >> 2) & 12))
#define PIO256 0.012271846303085129f   // pi/256
#define CW (-0.012271846303085129f)    // -2*pi/512

// ---------------- device scratch ----------------
__device__ float2 g_Y[(size_t)NB * NS * NFRM * NF];          // beamformed STFT [b][s][t][f]
__device__ float2 g_frames2[(size_t)NB * NS * NFRM * NHALF]; // windowed irfft frames (pairs)

__device__ __forceinline__ float2 cadd(float2 a, float2 b) { return make_float2(a.x + b.x, a.y + b.y); }
__device__ __forceinline__ float2 csub(float2 a, float2 b) { return make_float2(a.x - b.x, a.y - b.y); }
__device__ __forceinline__ float2 cmul(float2 a, float2 w) {
    return make_float2(a.x * w.x - a.y * w.y, a.x * w.y + a.y * w.x);
}

__device__ __forceinline__ int reflect_idx(int i) {
    i = (i < 0) ? -i : i;
    return (i >= NT) ? (2 * NT - 2 - i) : i;
}

// ============ FUSED: STFT + beamform + inverse rfft + window; one block/(b,t) ============
// R13 champion + (a) fwd stage-3 outputs kept in regs (saves 4 LDS), (b) 0.5-factor folding.
__global__ __launch_bounds__(128, 9) void k_fused(
    const float* __restrict__ x,
    const float* __restrict__ sr, const float* __restrict__ si
) {
    int bt = blockIdx.x;
    int b = bt / NFRM, t = bt - b * NFRM;
    int tid = threadIdx.x;
    int c = tid >> 6, j = tid & 63;

    __shared__ float2 buf[2][2][NHALF];
    __shared__ float2 sX[2][NF];   // holds 2X (scale folded into beamform)
    __shared__ float2 sY[2][NF];

    float wl[4], wh[4], ucs[4], usn[4];
#pragma unroll
    for (int q = 0; q < 4; q++) {
        int k = j + 64 * q;
        wl[q] = 0.5f - 0.5f * __cosf(PIO256 * (float)(2 * k));
        wh[q] = 0.5f - 0.5f * __cosf(PIO256 * (float)(2 * k + 1));
        __sincosf(CW * (float)k, &usn[q], &ucs[q]);
    }
    float fcs[3], fsn[3];
    {
        int tb1 = (j & 3) << 5, tb2 = (j & 15) << 3, tb3 = j << 1;
        __sincosf(CW * (float)tb1, &fsn[0], &fcs[0]);
        __sincosf(CW * (float)tb2, &fsn[1], &fcs[1]);
        __sincosf(CW * (float)tb3, &fsn[2], &fcs[2]);
    }

    const float* xin = x + (size_t)(b * NC + c) * NT;
    int base = t * HOP - PADN;
    float2 v[4];
    if (t >= 2 && t <= 2498) {
        const float2* x2 = (const float2*)(xin + base);
#pragma unroll
        for (int q = 0; q < 4; q++) {
            float2 xx = x2[j + 64 * q];
            v[q] = make_float2(xx.x * wl[q], xx.y * wh[q]);
        }
    } else {
#pragma unroll
        for (int q = 0; q < 4; q++) {
            int i0 = base + 2 * (j + 64 * q);
            v[q] = make_float2(xin[reflect_idx(i0)] * wl[q],
                               xin[reflect_idx(i0 + 1)] * wh[q]);
        }
    }

    // ---- forward radix-4 Stockham, stage 0 in registers, STS.128 ----
    {
        float2 s0 = cadd(v[0], v[2]), d0 = csub(v[0], v[2]);
        float2 s1 = cadd(v[1], v[3]), d1 = csub(v[1], v[3]);
        float2 c0 = cadd(s0, s1);
        float2 c1 = make_float2(d0.x + d1.y, d0.y - d1.x);
        float2 c2 = csub(s0, s1);
        float2 c3 = make_float2(d0.x - d1.y, d0.y + d1.x);
        float4* dst = (float4*)&buf[c][0][SWZ(4 * j)];
        dst[0] = make_float4(c0.x, c0.y, c1.x, c1.y);
        dst[1] = make_float4(c2.x, c2.y, c3.x, c3.y);
    }
    __syncthreads();

    int p = 0;
#pragma unroll
    for (int st = 1; st < 3; st++) {
        int Ns = 1 << (2 * st);
        int r = j & (Ns - 1);
        float2 w1 = make_float2(fcs[st - 1], fsn[st - 1]);
        float2 w2 = cmul(w1, w1);
        float2 w3 = cmul(w2, w1);
        float2 a0 = buf[c][p][SWZ(j)];
        float2 a1 = cmul(buf[c][p][SWZ(j + 64)],  w1);
        float2 a2 = cmul(buf[c][p][SWZ(j + 128)], w2);
        float2 a3 = cmul(buf[c][p][SWZ(j + 192)], w3);
        float2 s0 = cadd(a0, a2), d0 = csub(a0, a2);
        float2 s1 = cadd(a1, a3), d1 = csub(a1, a3);
        int bse = ((j >> (2 * st)) << (2 * st + 2)) + r;
        buf[c][p ^ 1][SWZ(bse)]          = cadd(s0, s1);
        buf[c][p ^ 1][SWZ(bse + Ns)]     = make_float2(d0.x + d1.y, d0.y - d1.x);
        buf[c][p ^ 1][SWZ(bse + 2 * Ns)] = csub(s0, s1);
        buf[c][p ^ 1][SWZ(bse + 3 * Ns)] = make_float2(d0.x - d1.y, d0.y + d1.x);
        p ^= 1;
        __syncthreads();
    }

    // ---- forward stage 3 (Ns=64): outputs k=j+64q kept in registers + stored ----
    float2 zz[4];
    {
        float2 w1 = make_float2(fcs[2], fsn[2]);
        float2 w2 = cmul(w1, w1);
        float2 w3 = cmul(w2, w1);
        float2 a0 = buf[c][p][SWZ(j)];
        float2 a1 = cmul(buf[c][p][SWZ(j + 64)],  w1);
        float2 a2 = cmul(buf[c][p][SWZ(j + 128)], w2);
        float2 a3 = cmul(buf[c][p][SWZ(j + 192)], w3);
        float2 s0 = cadd(a0, a2), d0 = csub(a0, a2);
        float2 s1 = cadd(a1, a3), d1 = csub(a1, a3);
        zz[0] = cadd(s0, s1);
        zz[1] = make_float2(d0.x + d1.y, d0.y - d1.x);
        zz[2] = csub(s0, s1);
        zz[3] = make_float2(d0.x - d1.y, d0.y + d1.x);
        buf[c][p ^ 1][SWZ(j)]       = zz[0];
        buf[c][p ^ 1][SWZ(j + 64)]  = zz[1];
        buf[c][p ^ 1][SWZ(j + 128)] = zz[2];
        buf[c][p ^ 1][SWZ(j + 192)] = zz[3];
        p ^= 1;
    }
    __syncthreads();

    // ---- unpack to rfft bins: Zk from regs, Zm from smem; store 2X (no 0.5) ----
#pragma unroll
    for (int q = 0; q < 4; q++) {
        int k = j + 64 * q;
        float2 Zk = zz[q];
        float2 Zm = buf[c][p][SWZ((256 - k) & 255)];
        float Ex = Zk.x + Zm.x, Ey = Zk.y - Zm.y;
        float Dx = Zk.x - Zm.x, Dy = Zk.y + Zm.y;
        float Ox = Dy, Oy = -Dx;
        sX[c][k] = make_float2(Ex + (Ox * ucs[q] - Oy * usn[q]),
                               Ey + (Ox * usn[q] + Oy * ucs[q]));
    }
    if (j == 0) {
        sX[c][256] = make_float2(2.0f * (zz[0].x - zz[0].y), 0.0f);
    }
    __syncthreads();

    // ---- beamform (inv carries the 0.5 compensation): write g_Y and sY ----
    float2* Yout = g_Y + ((size_t)(b * NS) * NFRM + t) * NF;
    for (int item = tid; item < NS * NF; item += 128) {
        int s = (item >= NF);
        int k = item - s * NF;
        float2 arv = ((const float2*)sr)[item];
        float2 aiv = ((const float2*)si)[item];
        float inv = 0.5f / (arv.x * arv.x + aiv.x * aiv.x +
                            arv.y * arv.y + aiv.y * aiv.y);
        float2 X0 = sX[0][k], X1 = sX[1][k];
        float2 y = make_float2(
            inv * (arv.x * X0.x + aiv.x * X0.y + arv.y * X1.x + aiv.y * X1.y),
            inv * (arv.x * X0.y - aiv.x * X0.x + arv.y * X1.y - aiv.y * X1.x));
        sY[s][k] = y;
        Yout[(size_t)s * NFRM * NF + k] = y;
    }
    __syncthreads();

    // ---- inverse rfft from sY (0.5s dropped; final scale 1/512) ----
    int s = c;
    float2 z[4];
#pragma unroll
    for (int q = 0; q < 4; q++) {
        int k = j + 64 * q;
        float2 Xk = sY[s][k];
        float2 Xm = sY[s][256 - k];
        if (k == 0) { Xk.y = 0.0f; Xm.y = 0.0f; }  // irfft drops imag of bins 0, 256
        float Ex = Xk.x + Xm.x, Ey = Xk.y - Xm.y;
        float Dx = Xk.x - Xm.x, Dy = Xk.y + Xm.y;
        float Ox = Dx * ucs[q] + Dy * usn[q];   // D*conj(w)
        float Oy = Dy * ucs[q] - Dx * usn[q];
        z[q] = make_float2(Ex - Oy, Ey + Ox);   // 2*(E + i*O)
    }
    {
        float2 s0 = cadd(z[0], z[2]), d0 = csub(z[0], z[2]);
        float2 s1 = cadd(z[1], z[3]), d1 = csub(z[1], z[3]);
        float2 c0 = cadd(s0, s1);
        float2 c1 = make_float2(d0.x - d1.y, d0.y + d1.x);
        float2 c2 = csub(s0, s1);
        float2 c3 = make_float2(d0.x + d1.y, d0.y - d1.x);
        float4* dst = (float4*)&buf[s][0][SWZ(4 * j)];
        dst[0] = make_float4(c0.x, c0.y, c1.x, c1.y);
        dst[1] = make_float4(c2.x, c2.y, c3.x, c3.y);
    }
    __syncthreads();

    p = 0;
#pragma unroll
    for (int st = 1; st < 3; st++) {
        int Ns = 1 << (2 * st);
        int r = j & (Ns - 1);
        float2 w1 = make_float2(fcs[st - 1], -fsn[st - 1]);  // conj
        float2 w2 = cmul(w1, w1);
        float2 w3 = cmul(w2, w1);
        float2 a0 = buf[s][p][SWZ(j)];
        float2 a1 = cmul(buf[s][p][SWZ(j + 64)],  w1);
        float2 a2 = cmul(buf[s][p][SWZ(j + 128)], w2);
        float2 a3 = cmul(buf[s][p][SWZ(j + 192)], w3);
        float2 s0 = cadd(a0, a2), d0 = csub(a0, a2);
        float2 s1 = cadd(a1, a3), d1 = csub(a1, a3);
        int bse = ((j >> (2 * st)) << (2 * st + 2)) + r;
        buf[s][p ^ 1][SWZ(bse)]          = cadd(s0, s1);
        buf[s][p ^ 1][SWZ(bse + Ns)]     = make_float2(d0.x - d1.y, d0.y + d1.x);
        buf[s][p ^ 1][SWZ(bse + 2 * Ns)] = csub(s0, s1);
        buf[s][p ^ 1][SWZ(bse + 3 * Ns)] = make_float2(d0.x + d1.y, d0.y - d1.x);
        p ^= 1;
        __syncthreads();
    }

    // stage 3 (Ns=64): outputs at j+64q -> windowed frame to gmem (scale 1/512)
    {
        float2 w1 = make_float2(fcs[2], -fsn[2]);
        float2 w2 = cmul(w1, w1);
        float2 w3 = cmul(w2, w1);
        float2 a0 = buf[s][p][SWZ(j)];
        float2 a1 = cmul(buf[s][p][SWZ(j + 64)],  w1);
        float2 a2 = cmul(buf[s][p][SWZ(j + 128)], w2);
        float2 a3 = cmul(buf[s][p][SWZ(j + 192)], w3);
        float2 s0 = cadd(a0, a2), d0 = csub(a0, a2);
        float2 s1 = cadd(a1, a3), d1 = csub(a1, a3);
        float2 cc[4];
        cc[0] = cadd(s0, s1);
        cc[1] = make_float2(d0.x - d1.y, d0.y + d1.x);
        cc[2] = csub(s0, s1);
        cc[3] = make_float2(d0.x + d1.y, d0.y - d1.x);
        float2* fout = g_frames2 + ((size_t)(b * NS + s) * NFRM + t) * NHALF;
        const float sc = 1.0f / 512.0f;
#pragma unroll
        for (int q = 0; q < 4; q++) {
            fout[j + 64 * q] = make_float2(cc[q].x * sc * wl[q],
                                           cc[q].y * sc * wh[q]);
        }
    }
}

// ---------------- transpose Y [t][f] -> planar output [f][t] per (b,s) ----------------
__global__ void k_transpose(float* __restrict__ reOut, float* __restrict__ imOut,
                            unsigned long long planeCap) {
    __shared__ float2 tile[32][33];
    int bs = blockIdx.z;
    int f0 = blockIdx.x << 5, t0 = blockIdx.y << 5;
    const float2* src = g_Y + (size_t)bs * NFRM * NF;
#pragma unroll
    for (int i = 0; i < 4; i++) {
        int tt = t0 + threadIdx.y + i * 8, ff = f0 + threadIdx.x;
        if (tt < NFRM && ff < NF)
            tile[threadIdx.y + i * 8][threadIdx.x] = src[(size_t)tt * NF + ff];
    }
    __syncthreads();
    size_t dbase = (size_t)bs * NF * NFRM;
#pragma unroll
    for (int i = 0; i < 4; i++) {
        int ff = f0 + threadIdx.y + i * 8, tt = t0 + threadIdx.x;
        if (ff < NF && tt < NFRM) {
            size_t di = dbase + (size_t)ff * NFRM + tt;
            if (di < planeCap) {
                float2 v = tile[threadIdx.x][threadIdx.y + i * 8];
                reOut[di] = v.x;
                if (imOut) imOut[di] = v.y;
            }
        }
    }
}

// ---------------- overlap-add (4 samples/thread, analytic envelope) ----------------
__global__ void k_combine(float* __restrict__ yt, unsigned long long cap) {
    int idx = blockIdx.x * blockDim.x + threadIdx.x;
    const int quarter = NT / 4;
    if (idx >= NB * NS * quarter) return;
    int bs = idx / quarter;
    int mo = (idx - bs * quarter) * 4;
    int m = mo + PADN;
    int klo = m - 384;
    klo = (klo < 0) ? 0 : (klo >> 7);
    int khi = m >> 7;
    if (khi > NFRM - 1) khi = NFRM - 1;
    const float4* fr4 = (const float4*)(g_frames2 + (size_t)bs * NFRM * NHALF);
    float y0 = 0, y1 = 0, y2 = 0, y3 = 0;
    for (int k = klo; k <= khi; k++) {
        int r = m - (k << 7);   // multiple of 4, <= 508
        float4 vv = fr4[k * 128 + (r >> 2)];
        y0 += vv.x; y1 += vv.y; y2 += vv.z; y3 += vv.w;
    }
    float4 out;
    if (mo >= 128 && mo <= 319868) {
        const float inv = 2.0f / 3.0f;  // Hann^2 COLA envelope = 3/2
        out = make_float4(y0 * inv, y1 * inv, y2 * inv, y3 * inv);
    } else {
        float e0 = 0, e1 = 0, e2 = 0, e3 = 0;
        for (int k = klo; k <= khi; k++) {
            int r = m - (k << 7);
            float a0 = 0.5f - 0.5f * __cosf(PIO256 * (float)r);
            float a1 = 0.5f - 0.5f * __cosf(PIO256 * (float)(r + 1));
            float a2 = 0.5f - 0.5f * __cosf(PIO256 * (float)(r + 2));
            float a3 = 0.5f - 0.5f * __cosf(PIO256 * (float)(r + 3));
            e0 += a0 * a0; e1 += a1 * a1; e2 += a2 * a2; e3 += a3 * a3;
        }
        out = make_float4(y0 / e0, y1 / e1, y2 / e2, y3 / e3);
    }
    size_t i0 = (size_t)(bs * 2) * NT + mo;
    size_t i1 = (size_t)(bs * 2 + 1) * NT + mo;
    if (i0 + 3 < cap) *(float4*)(yt + i0) = out;
    if (i1 + 3 < cap) *(float4*)(yt + i1) = out;
}

// ---------------- launcher ----------------
extern "C" void kernel_launch(void* const* d_in, const int* in_sizes, int n_in,
                              void* d_out, int out_size) {
    const float* x = 0; const float* small[2] = {0, 0}; int nsmall = 0;
    for (int i = 0; i < n_in && i < 3; i++) {
        if (in_sizes[i] > 1000000) x = (const float*)d_in[i];
        else if (nsmall < 2) small[nsmall++] = (const float*)d_in[i];
    }
    const float* sr = small[0] ? small[0] : (const float*)d_in[1];
    const float* si = small[1] ? small[1] : (const float*)d_in[2];
    if (!x) x = (const float*)d_in[0];

    size_t osz = (size_t)out_size;
    float* base = (float*)d_out;

    float* yt = 0;  unsigned long long ytCap = 0;
    float* re = 0;  float* im = 0;  unsigned long long planeCap = 0;

    if (osz == YT_N + YB_N) {
        yt = base;              ytCap = YT_N;
        re = base + YT_N;       im = base + YT_N + YB_E;   planeCap = YB_E;
    } else if (osz == YT_N + YB_E) {
        yt = base;              ytCap = YT_N;
        re = base + YT_N;       im = 0;                    planeCap = YB_E;
    } else if (osz == YT_N) {
        yt = base;              ytCap = YT_N;
    } else if (osz == YB_N) {
        re = base;              im = base + YB_E;          planeCap = YB_E;
    } else if (osz == YB_E) {
        re = base;              im = 0;                    planeCap = YB_E;
    } else {
        yt = base;              ytCap = (osz < YT_N) ? osz : YT_N;
        if (osz > YT_N) {
            size_t rem = osz - YT_N;
            re = base + YT_N;
            if (rem >= 2 * YB_E) { im = base + YT_N + YB_E; planeCap = YB_E; }
            else                 { im = 0; planeCap = rem; }
        }
    }

    k_fused<<<NB * NFRM, 128>>>(x, sr, si);
    if (re) {
        dim3 tg((NF + 31) / 32, (NFRM + 31) / 32, NB * NS);
        k_transpose<<<tg, dim3(32, 8)>>>(re, im, planeCap);
    }
    if (yt) {
        k_combine<<<(NB * NS * (NT / 4) + 255) / 256, 256>>>(yt, ytCap);
    }
}

// round 17
// speedup vs baseline: 1.0475x; 1.0167x over previous
#include <cuda_runtime.h>
#include <math.h>

#define NB   16
#define NC   2
#define NS   2
#define NF   257
#define NHALF 256
#define HOP  128
#define PADN 256
#define NFRM 2501
#define NT   320000

#define YT_N ((size_t)NB * NS * NC * NT)          // 20,480,000 floats (y_time)
#define YB_E ((size_t)NB * NS * NF * NFRM)        // 20,568,224 complex elements
#define YB_N (YB_E * 2)                           // 41,136,448 floats (re+im)

#define SWZ(k) ((k) ^ (((k) >> 2) & 12))
#define PIO256 0.012271846303085129f   // pi/256
#define CW (-0.012271846303085129f)    // -2*pi/512

// ---------------- device scratch ----------------
__device__ float2 g_Y[(size_t)NB * NS * NFRM * NF];          // beamformed STFT [b][s][t][f]
__device__ float2 g_frames2[(size_t)NB * NS * NFRM * NHALF]; // windowed irfft frames (pairs)

__device__ __forceinline__ float2 cadd(float2 a, float2 b) { return make_float2(a.x + b.x, a.y + b.y); }
__device__ __forceinline__ float2 csub(float2 a, float2 b) { return make_float2(a.x - b.x, a.y - b.y); }
__device__ __forceinline__ float2 cmul(float2 a, float2 w) {
    return make_float2(a.x * w.x - a.y * w.y, a.x * w.y + a.y * w.x);
}

__device__ __forceinline__ int reflect_idx(int i) {
    i = (i < 0) ? -i : i;
    return (i >= NT) ? (2 * NT - 2 - i) : i;
}

// ============ FUSED: STFT + beamform + inverse rfft + window; one block/(b,t) ============
// R16 champion + beamform re-mapped to (c, j+64q) so y stays in registers into the
// inverse pack (saves 4 LDS.64/thread).
__global__ __launch_bounds__(128, 9) void k_fused(
    const float* __restrict__ x,
    const float* __restrict__ sr, const float* __restrict__ si
) {
    int bt = blockIdx.x;
    int b = bt / NFRM, t = bt - b * NFRM;
    int tid = threadIdx.x;
    int c = tid >> 6, j = tid & 63;

    __shared__ float2 buf[2][2][NHALF];
    __shared__ float2 sX[2][NF];   // holds 2X (scale folded into beamform)
    __shared__ float2 sY[2][NF];

    float wl[4], wh[4], ucs[4], usn[4];
#pragma unroll
    for (int q = 0; q < 4; q++) {
        int k = j + 64 * q;
        wl[q] = 0.5f - 0.5f * __cosf(PIO256 * (float)(2 * k));
        wh[q] = 0.5f - 0.5f * __cosf(PIO256 * (float)(2 * k + 1));
        __sincosf(CW * (float)k, &usn[q], &ucs[q]);
    }
    float fcs[3], fsn[3];
    {
        int tb1 = (j & 3) << 5, tb2 = (j & 15) << 3, tb3 = j << 1;
        __sincosf(CW * (float)tb1, &fsn[0], &fcs[0]);
        __sincosf(CW * (float)tb2, &fsn[1], &fcs[1]);
        __sincosf(CW * (float)tb3, &fsn[2], &fcs[2]);
    }

    const float* xin = x + (size_t)(b * NC + c) * NT;
    int base = t * HOP - PADN;
    float2 v[4];
    if (t >= 2 && t <= 2498) {
        const float2* x2 = (const float2*)(xin + base);
#pragma unroll
        for (int q = 0; q < 4; q++) {
            float2 xx = x2[j + 64 * q];
            v[q] = make_float2(xx.x * wl[q], xx.y * wh[q]);
        }
    } else {
#pragma unroll
        for (int q = 0; q < 4; q++) {
            int i0 = base + 2 * (j + 64 * q);
            v[q] = make_float2(xin[reflect_idx(i0)] * wl[q],
                               xin[reflect_idx(i0 + 1)] * wh[q]);
        }
    }

    // ---- forward radix-4 Stockham, stage 0 in registers, STS.128 ----
    {
        float2 s0 = cadd(v[0], v[2]), d0 = csub(v[0], v[2]);
        float2 s1 = cadd(v[1], v[3]), d1 = csub(v[1], v[3]);
        float2 c0 = cadd(s0, s1);
        float2 c1 = make_float2(d0.x + d1.y, d0.y - d1.x);
        float2 c2 = csub(s0, s1);
        float2 c3 = make_float2(d0.x - d1.y, d0.y + d1.x);
        float4* dst = (float4*)&buf[c][0][SWZ(4 * j)];
        dst[0] = make_float4(c0.x, c0.y, c1.x, c1.y);
        dst[1] = make_float4(c2.x, c2.y, c3.x, c3.y);
    }
    __syncthreads();

    int p = 0;
#pragma unroll
    for (int st = 1; st < 3; st++) {
        int Ns = 1 << (2 * st);
        int r = j & (Ns - 1);
        float2 w1 = make_float2(fcs[st - 1], fsn[st - 1]);
        float2 w2 = cmul(w1, w1);
        float2 w3 = cmul(w2, w1);
        float2 a0 = buf[c][p][SWZ(j)];
        float2 a1 = cmul(buf[c][p][SWZ(j + 64)],  w1);
        float2 a2 = cmul(buf[c][p][SWZ(j + 128)], w2);
        float2 a3 = cmul(buf[c][p][SWZ(j + 192)], w3);
        float2 s0 = cadd(a0, a2), d0 = csub(a0, a2);
        float2 s1 = cadd(a1, a3), d1 = csub(a1, a3);
        int bse = ((j >> (2 * st)) << (2 * st + 2)) + r;
        buf[c][p ^ 1][SWZ(bse)]          = cadd(s0, s1);
        buf[c][p ^ 1][SWZ(bse + Ns)]     = make_float2(d0.x + d1.y, d0.y - d1.x);
        buf[c][p ^ 1][SWZ(bse + 2 * Ns)] = csub(s0, s1);
        buf[c][p ^ 1][SWZ(bse + 3 * Ns)] = make_float2(d0.x - d1.y, d0.y + d1.x);
        p ^= 1;
        __syncthreads();
    }

    // ---- forward stage 3 (Ns=64): outputs k=j+64q kept in registers + stored ----
    float2 zz[4];
    {
        float2 w1 = make_float2(fcs[2], fsn[2]);
        float2 w2 = cmul(w1, w1);
        float2 w3 = cmul(w2, w1);
        float2 a0 = buf[c][p][SWZ(j)];
        float2 a1 = cmul(buf[c][p][SWZ(j + 64)],  w1);
        float2 a2 = cmul(buf[c][p][SWZ(j + 128)], w2);
        float2 a3 = cmul(buf[c][p][SWZ(j + 192)], w3);
        float2 s0 = cadd(a0, a2), d0 = csub(a0, a2);
        float2 s1 = cadd(a1, a3), d1 = csub(a1, a3);
        zz[0] = cadd(s0, s1);
        zz[1] = make_float2(d0.x + d1.y, d0.y - d1.x);
        zz[2] = csub(s0, s1);
        zz[3] = make_float2(d0.x - d1.y, d0.y + d1.x);
        buf[c][p ^ 1][SWZ(j)]       = zz[0];
        buf[c][p ^ 1][SWZ(j + 64)]  = zz[1];
        buf[c][p ^ 1][SWZ(j + 128)] = zz[2];
        buf[c][p ^ 1][SWZ(j + 192)] = zz[3];
        p ^= 1;
    }
    __syncthreads();

    // ---- unpack to rfft bins: Zk from regs, Zm from smem; store 2X (no 0.5) ----
#pragma unroll
    for (int q = 0; q < 4; q++) {
        int k = j + 64 * q;
        float2 Zk = zz[q];
        float2 Zm = buf[c][p][SWZ((256 - k) & 255)];
        float Ex = Zk.x + Zm.x, Ey = Zk.y - Zm.y;
        float Dx = Zk.x - Zm.x, Dy = Zk.y + Zm.y;
        float Ox = Dy, Oy = -Dx;
        sX[c][k] = make_float2(Ex + (Ox * ucs[q] - Oy * usn[q]),
                               Ey + (Ox * usn[q] + Oy * ucs[q]));
    }
    if (j == 0) {
        sX[c][256] = make_float2(2.0f * (zz[0].x - zz[0].y), 0.0f);
    }
    __syncthreads();

    // ---- beamform with pack-aligned mapping: thread (c,j) computes sY[c][j+64q] ----
    // yv stays in registers for the inverse pack below.
    float2 yv[4];
    float2* Yout = g_Y + (((size_t)(b * NS + c)) * NFRM + t) * NF;
#pragma unroll
    for (int q = 0; q < 4; q++) {
        int k = j + 64 * q;
        int item = c * NF + k;
        float2 arv = ((const float2*)sr)[item];
        float2 aiv = ((const float2*)si)[item];
        float inv = 0.5f / (arv.x * arv.x + aiv.x * aiv.x +
                            arv.y * arv.y + aiv.y * aiv.y);
        float2 X0 = sX[0][k], X1 = sX[1][k];
        yv[q] = make_float2(
            inv * (arv.x * X0.x + aiv.x * X0.y + arv.y * X1.x + aiv.y * X1.y),
            inv * (arv.x * X0.y - aiv.x * X0.x + arv.y * X1.y - aiv.y * X1.x));
        sY[c][k] = yv[q];
        Yout[k] = yv[q];
    }
    if (j == 0) {   // bin 256, own steer c
        int item = c * NF + 256;
        float2 arv = ((const float2*)sr)[item];
        float2 aiv = ((const float2*)si)[item];
        float inv = 0.5f / (arv.x * arv.x + aiv.x * aiv.x +
                            arv.y * arv.y + aiv.y * aiv.y);
        float2 X0 = sX[0][256], X1 = sX[1][256];
        float2 y = make_float2(
            inv * (arv.x * X0.x + aiv.x * X0.y + arv.y * X1.x + aiv.y * X1.y),
            inv * (arv.x * X0.y - aiv.x * X0.x + arv.y * X1.y - aiv.y * X1.x));
        sY[c][256] = y;
        Yout[256] = y;
    }
    __syncthreads();

    // ---- inverse rfft: Xk from yv regs, mirror from smem ----
    int s = c;
    float2 z[4];
#pragma unroll
    for (int q = 0; q < 4; q++) {
        int k = j + 64 * q;
        float2 Xk = yv[q];
        float2 Xm = sY[s][256 - k];
        if (k == 0) { Xk.y = 0.0f; Xm.y = 0.0f; }  // irfft drops imag of bins 0, 256
        float Ex = Xk.x + Xm.x, Ey = Xk.y - Xm.y;
        float Dx = Xk.x - Xm.x, Dy = Xk.y + Xm.y;
        float Ox = Dx * ucs[q] + Dy * usn[q];   // D*conj(w)
        float Oy = Dy * ucs[q] - Dx * usn[q];
        z[q] = make_float2(Ex - Oy, Ey + Ox);   // 2*(E + i*O)
    }
    {
        float2 s0 = cadd(z[0], z[2]), d0 = csub(z[0], z[2]);
        float2 s1 = cadd(z[1], z[3]), d1 = csub(z[1], z[3]);
        float2 c0 = cadd(s0, s1);
        float2 c1 = make_float2(d0.x - d1.y, d0.y + d1.x);
        float2 c2 = csub(s0, s1);
        float2 c3 = make_float2(d0.x + d1.y, d0.y - d1.x);
        float4* dst = (float4*)&buf[s][0][SWZ(4 * j)];
        dst[0] = make_float4(c0.x, c0.y, c1.x, c1.y);
        dst[1] = make_float4(c2.x, c2.y, c3.x, c3.y);
    }
    __syncthreads();

    p = 0;
#pragma unroll
    for (int st = 1; st < 3; st++) {
        int Ns = 1 << (2 * st);
        int r = j & (Ns - 1);
        float2 w1 = make_float2(fcs[st - 1], -fsn[st - 1]);  // conj
        float2 w2 = cmul(w1, w1);
        float2 w3 = cmul(w2, w1);
        float2 a0 = buf[s][p][SWZ(j)];
        float2 a1 = cmul(buf[s][p][SWZ(j + 64)],  w1);
        float2 a2 = cmul(buf[s][p][SWZ(j + 128)], w2);
        float2 a3 = cmul(buf[s][p][SWZ(j + 192)], w3);
        float2 s0 = cadd(a0, a2), d0 = csub(a0, a2);
        float2 s1 = cadd(a1, a3), d1 = csub(a1, a3);
        int bse = ((j >> (2 * st)) << (2 * st + 2)) + r;
        buf[s][p ^ 1][SWZ(bse)]          = cadd(s0, s1);
        buf[s][p ^ 1][SWZ(bse + Ns)]     = make_float2(d0.x - d1.y, d0.y + d1.x);
        buf[s][p ^ 1][SWZ(bse + 2 * Ns)] = csub(s0, s1);
        buf[s][p ^ 1][SWZ(bse + 3 * Ns)] = make_float2(d0.x + d1.y, d0.y - d1.x);
        p ^= 1;
        __syncthreads();
    }

    // stage 3 (Ns=64): outputs at j+64q -> windowed frame to gmem (scale 1/512)
    {
        float2 w1 = make_float2(fcs[2], -fsn[2]);
        float2 w2 = cmul(w1, w1);
        float2 w3 = cmul(w2, w1);
        float2 a0 = buf[s][p][SWZ(j)];
        float2 a1 = cmul(buf[s][p][SWZ(j + 64)],  w1);
        float2 a2 = cmul(buf[s][p][SWZ(j + 128)], w2);
        float2 a3 = cmul(buf[s][p][SWZ(j + 192)], w3);
        float2 s0 = cadd(a0, a2), d0 = csub(a0, a2);
        float2 s1 = cadd(a1, a3), d1 = csub(a1, a3);
        float2 cc[4];
        cc[0] = cadd(s0, s1);
        cc[1] = make_float2(d0.x - d1.y, d0.y + d1.x);
        cc[2] = csub(s0, s1);
        cc[3] = make_float2(d0.x + d1.y, d0.y - d1.x);
        float2* fout = g_frames2 + ((size_t)(b * NS + s) * NFRM + t) * NHALF;
        const float sc = 1.0f / 512.0f;
#pragma unroll
        for (int q = 0; q < 4; q++) {
            fout[j + 64 * q] = make_float2(cc[q].x * sc * wl[q],
                                           cc[q].y * sc * wh[q]);
        }
    }
}

// ---------------- transpose Y [t][f] -> planar output [f][t] per (b,s) ----------------
__global__ void k_transpose(float* __restrict__ reOut, float* __restrict__ imOut,
                            unsigned long long planeCap) {
    __shared__ float2 tile[32][33];
    int bs = blockIdx.z;
    int f0 = blockIdx.x << 5, t0 = blockIdx.y << 5;
    const float2* src = g_Y + (size_t)bs * NFRM * NF;
#pragma unroll
    for (int i = 0; i < 4; i++) {
        int tt = t0 + threadIdx.y + i * 8, ff = f0 + threadIdx.x;
        if (tt < NFRM && ff < NF)
            tile[threadIdx.y + i * 8][threadIdx.x] = src[(size_t)tt * NF + ff];
    }
    __syncthreads();
    size_t dbase = (size_t)bs * NF * NFRM;
#pragma unroll
    for (int i = 0; i < 4; i++) {
        int ff = f0 + threadIdx.y + i * 8, tt = t0 + threadIdx.x;
        if (ff < NF && tt < NFRM) {
            size_t di = dbase + (size_t)ff * NFRM + tt;
            if (di < planeCap) {
                float2 v = tile[threadIdx.x][threadIdx.y + i * 8];
                reOut[di] = v.x;
                if (imOut) imOut[di] = v.y;
            }
        }
    }
}

// ---------------- overlap-add (4 samples/thread, analytic envelope) ----------------
__global__ void k_combine(float* __restrict__ yt, unsigned long long cap) {
    int idx = blockIdx.x * blockDim.x + threadIdx.x;
    const int quarter = NT / 4;
    if (idx >= NB * NS * quarter) return;
    int bs = idx / quarter;
    int mo = (idx - bs * quarter) * 4;
    int m = mo + PADN;
    int klo = m - 384;
    klo = (klo < 0) ? 0 : (klo >> 7);
    int khi = m >> 7;
    if (khi > NFRM - 1) khi = NFRM - 1;
    const float4* fr4 = (const float4*)(g_frames2 + (size_t)bs * NFRM * NHALF);
    float y0 = 0, y1 = 0, y2 = 0, y3 = 0;
    for (int k = klo; k <= khi; k++) {
        int r = m - (k << 7);   // multiple of 4, <= 508
        float4 vv = fr4[k * 128 + (r >> 2)];
        y0 += vv.x; y1 += vv.y; y2 += vv.z; y3 += vv.w;
    }
    float4 out;
    if (mo >= 128 && mo <= 319868) {
        const float inv = 2.0f / 3.0f;  // Hann^2 COLA envelope = 3/2
        out = make_float4(y0 * inv, y1 * inv, y2 * inv, y3 * inv);
    } else {
        float e0 = 0, e1 = 0, e2 = 0, e3 = 0;
        for (int k = klo; k <= khi; k++) {
            int r = m - (k << 7);
            float a0 = 0.5f - 0.5f * __cosf(PIO256 * (float)r);
            float a1 = 0.5f - 0.5f * __cosf(PIO256 * (float)(r + 1));
            float a2 = 0.5f - 0.5f * __cosf(PIO256 * (float)(r + 2));
            float a3 = 0.5f - 0.5f * __cosf(PIO256 * (float)(r + 3));
            e0 += a0 * a0; e1 += a1 * a1; e2 += a2 * a2; e3 += a3 * a3;
        }
        out = make_float4(y0 / e0, y1 / e1, y2 / e2, y3 / e3);
    }
    size_t i0 = (size_t)(bs * 2) * NT + mo;
    size_t i1 = (size_t)(bs * 2 + 1) * NT + mo;
    if (i0 + 3 < cap) *(float4*)(yt + i0) = out;
    if (i1 + 3 < cap) *(float4*)(yt + i1) = out;
}

// ---------------- launcher ----------------
extern "C" void kernel_launch(void* const* d_in, const int* in_sizes, int n_in,
                              void* d_out, int out_size) {
    const float* x = 0; const float* small[2] = {0, 0}; int nsmall = 0;
    for (int i = 0; i < n_in && i < 3; i++) {
        if (in_sizes[i] > 1000000) x = (const float*)d_in[i];
        else if (nsmall < 2) small[nsmall++] = (const float*)d_in[i];
    }
    const float* sr = small[0] ? small[0] : (const float*)d_in[1];
    const float* si = small[1] ? small[1] : (const float*)d_in[2];
    if (!x) x = (const float*)d_in[0];

    size_t osz = (size_t)out_size;
    float* base = (float*)d_out;

    float* yt = 0;  unsigned long long ytCap = 0;
    float* re = 0;  float* im = 0;  unsigned long long planeCap = 0;

    if (osz == YT_N + YB_N) {
        yt = base;              ytCap = YT_N;
        re = base + YT_N;       im = base + YT_N + YB_E;   planeCap = YB_E;
    } else if (osz == YT_N + YB_E) {
        yt = base;              ytCap = YT_N;
        re = base + YT_N;       im = 0;                    planeCap = YB_E;
    } else if (osz == YT_N) {
        yt = base;              ytCap = YT_N;
    } else if (osz == YB_N) {
        re = base;              im = base + YB_E;          planeCap = YB_E;
    } else if (osz == YB_E) {
        re = base;              im = 0;                    planeCap = YB_E;
    } else {
        yt = base;              ytCap = (osz < YT_N) ? osz : YT_N;
        if (osz > YT_N) {
            size_t rem = osz - YT_N;
            re = base + YT_N;
            if (rem >= 2 * YB_E) { im = base + YT_N + YB_E; planeCap = YB_E; }
            else                 { im = 0; planeCap = rem; }
        }
    }

    k_fused<<<NB * NFRM, 128>>>(x, sr, si);
    if (re) {
        dim3 tg((NF + 31) / 32, (NFRM + 31) / 32, NB * NS);
        k_transpose<<<tg, dim3(32, 8)>>>(re, im, planeCap);
    }
    if (yt) {
        k_combine<<<(NB * NS * (NT / 4) + 255) / 256, 256>>>(yt, ytCap);
    }
}